// round 9
// baseline (speedup 1.0000x reference)
#include <cuda_runtime.h>
#include <cuda_bf16.h>
#include <stdint.h>

#define TLEN  512
#define BATCH 64
#define EMBD  512
#define HD    512
#define NG    2048
#define LT    48
#define MR    (TLEN*BATCH)

__device__ __nv_bfloat16 g_A  [(size_t)MR*EMBD];
__device__ __nv_bfloat16 g_Wih[(size_t)2*NG*EMBD];
__device__ __nv_bfloat16 g_Whh[(size_t)2*NG*HD];
__device__ float         g_bias[2*NG];
__device__ __nv_bfloat16 g_fcw[(size_t)128*1024];
__device__ __nv_bfloat16 g_G  [(size_t)2*MR*NG];
__device__ __nv_bfloat16 g_H  [(size_t)2*MR*HD];
__device__ float         g_em [(size_t)MR*LT];
__device__ float         g_llh[BATCH];
__device__ int           g_cnt[2];

__device__ __forceinline__ void cp_async16(void* smem, const void* gmem) {
    uint32_t s = (uint32_t)__cvta_generic_to_shared(smem);
    asm volatile("cp.async.cg.shared.global [%0], [%1], 16;\n" :: "r"(s), "l"(gmem));
}
__device__ __forceinline__ void cp_commit() { asm volatile("cp.async.commit_group;\n"); }
__device__ __forceinline__ void cp_wait0()  { asm volatile("cp.async.wait_group 0;\n"); }
__device__ __forceinline__ void cp_wait1()  { asm volatile("cp.async.wait_group 1;\n"); }

__device__ __forceinline__ void mma16816(float* c, const uint32_t* a, const uint32_t* b) {
    asm volatile("mma.sync.aligned.m16n8k16.row.col.f32.bf16.bf16.f32 "
                 "{%0,%1,%2,%3},{%4,%5,%6,%7},{%8,%9},{%0,%1,%2,%3};\n"
                 : "+f"(c[0]), "+f"(c[1]), "+f"(c[2]), "+f"(c[3])
                 : "r"(a[0]), "r"(a[1]), "r"(a[2]), "r"(a[3]), "r"(b[0]), "r"(b[1]));
}
__device__ __forceinline__ float tanh_f(float x) {
    float y; asm("tanh.approx.f32 %0, %1;" : "=f"(y) : "f"(x)); return y;
}
__device__ __forceinline__ float sig_f(float x) { return 1.f / (1.f + __expf(-x)); }
__device__ __forceinline__ int ld_acq(const int* p) {
    int v; asm volatile("ld.acquire.gpu.global.b32 %0, [%1];" : "=r"(v) : "l"(p)); return v;
}
__device__ __forceinline__ void red_add(int* p, int v) {
    asm volatile("red.global.add.s32 [%0], %1;" :: "l"(p), "r"(v));
}
__device__ __forceinline__ void bar_sync(int id, int cnt) {
    asm volatile("bar.sync %0, %1;" :: "r"(id), "r"(cnt) : "memory");
}

__global__ void k_reset() { if (threadIdx.x < 2) g_cnt[threadIdx.x] = 0; }

__global__ void k_prep(const float* wihf, const float* whhf, const float* bihf,
                       const float* bhhf, const float* wihb, const float* whhb,
                       const float* bihb, const float* bhhb, const float* fcw) {
    int id = blockIdx.x * blockDim.x + threadIdx.x;
    int st = gridDim.x * blockDim.x;
    const int NW = NG * EMBD;
    for (int i = id; i < NW; i += st) {
        g_Wih[i]      = __float2bfloat16(wihf[i]);
        g_Wih[NW + i] = __float2bfloat16(wihb[i]);
        g_Whh[i]      = __float2bfloat16(whhf[i]);
        g_Whh[NW + i] = __float2bfloat16(whhb[i]);
    }
    for (int i = id; i < NG; i += st) {
        g_bias[i]      = bihf[i] + bhhf[i];
        g_bias[NG + i] = bihb[i] + bhhb[i];
    }
    for (int i = id; i < 128 * 1024; i += st) {
        int l = i >> 10, k = i & 1023;
        g_fcw[i] = __float2bfloat16(l < LT ? fcw[l * 1024 + k] : 0.f);
    }
}

__global__ void k_gather(const float* emb, const int* x) {
    int id = blockIdx.x * 256 + threadIdx.x;
    int m = id >> 6, ch = id & 63;
    int t = m >> 6, b = m & 63;
    int tok = x[b * TLEN + t];
    const float4* s = (const float4*)(emb + (size_t)tok * EMBD + ch * 8);
    float4 u = s[0], v = s[1];
    __nv_bfloat162 pk[4];
    pk[0] = __float22bfloat162_rn(make_float2(u.x, u.y));
    pk[1] = __float22bfloat162_rn(make_float2(u.z, u.w));
    pk[2] = __float22bfloat162_rn(make_float2(v.x, v.y));
    pk[3] = __float22bfloat162_rn(make_float2(v.z, v.w));
    *(uint4*)(g_A + (size_t)m * EMBD + ch * 8) = *(const uint4*)pk;
}

// mode 0: G = A @ Wih^T + bias (bf16 out). mode 1: em = H @ fcw^T + fcb (fp32).
__global__ void __launch_bounds__(256, 2) k_gemm(int mode, const float* fcb) {
    __shared__ __nv_bfloat16 As[2][128 * 40];
    __shared__ __nv_bfloat16 Bs[2][128 * 40];
    int tid = threadIdx.x, lane = tid & 31, warp = tid >> 5;
    int wm = warp >> 2, wn = warp & 3;
    int m0 = blockIdx.y * 128, n0 = blockIdx.x * 128;
    int KC = mode ? 32 : 16;

    float acc[4][4][4];
    #pragma unroll
    for (int a = 0; a < 4; a++)
        #pragma unroll
        for (int b = 0; b < 4; b++)
            #pragma unroll
            for (int c = 0; c < 4; c++) acc[a][b][c] = 0.f;

    auto load_stage = [&](int kc, int s) {
        #pragma unroll
        for (int i = 0; i < 2; i++) {
            int c = tid + i * 256;
            int row = c >> 2, seg = c & 3;
            const __nv_bfloat16* sa;
            if (mode == 0)
                sa = g_A + (size_t)(m0 + row) * 512 + kc * 32 + seg * 8;
            else if (kc < 16)
                sa = g_H + (size_t)(m0 + row) * 512 + kc * 32 + seg * 8;
            else
                sa = g_H + (size_t)MR * HD + (size_t)(m0 + row) * 512 + (kc - 16) * 32 + seg * 8;
            cp_async16(&As[s][row * 40 + seg * 8], sa);
            const __nv_bfloat16* sb;
            if (mode == 0)
                sb = g_Wih + (size_t)(n0 + row) * 512 + kc * 32 + seg * 8;
            else
                sb = g_fcw + (size_t)(n0 + row) * 1024 + kc * 32 + seg * 8;
            cp_async16(&Bs[s][row * 40 + seg * 8], sb);
        }
    };

    load_stage(0, 0); cp_commit();
    for (int kc = 0; kc < KC; kc++) {
        int s = kc & 1;
        if (kc + 1 < KC) { load_stage(kc + 1, s ^ 1); cp_commit(); cp_wait1(); }
        else cp_wait0();
        __syncthreads();
        #pragma unroll
        for (int kk = 0; kk < 32; kk += 16) {
            int col = kk + (lane & 3) * 2;
            uint32_t a[4][4], bf[4][2];
            #pragma unroll
            for (int mi = 0; mi < 4; mi++) {
                int row = wm * 64 + mi * 16 + (lane >> 2);
                a[mi][0] = *(const uint32_t*)&As[s][row * 40 + col];
                a[mi][1] = *(const uint32_t*)&As[s][(row + 8) * 40 + col];
                a[mi][2] = *(const uint32_t*)&As[s][row * 40 + col + 8];
                a[mi][3] = *(const uint32_t*)&As[s][(row + 8) * 40 + col + 8];
            }
            #pragma unroll
            for (int ni = 0; ni < 4; ni++) {
                int n = wn * 32 + ni * 8 + (lane >> 2);
                bf[ni][0] = *(const uint32_t*)&Bs[s][n * 40 + col];
                bf[ni][1] = *(const uint32_t*)&Bs[s][n * 40 + col + 8];
            }
            #pragma unroll
            for (int mi = 0; mi < 4; mi++)
                #pragma unroll
                for (int ni = 0; ni < 4; ni++)
                    mma16816(acc[mi][ni], a[mi], bf[ni]);
        }
        __syncthreads();
    }

    #pragma unroll
    for (int mi = 0; mi < 4; mi++) {
        #pragma unroll
        for (int ni = 0; ni < 4; ni++) {
            int m = m0 + wm * 64 + mi * 16 + (lane >> 2);
            int n = n0 + wn * 32 + ni * 8 + (lane & 3) * 2;
            if (mode == 0) {
                int dir = n >> 11, r = n & 2047;
                size_t o1 = ((size_t)dir * MR + m) * NG + r;
                size_t o2 = ((size_t)dir * MR + m + 8) * NG + r;
                float b0 = g_bias[n], b1 = g_bias[n + 1];
                *(__nv_bfloat162*)&g_G[o1] = __float22bfloat162_rn(
                    make_float2(acc[mi][ni][0] + b0, acc[mi][ni][1] + b1));
                *(__nv_bfloat162*)&g_G[o2] = __float22bfloat162_rn(
                    make_float2(acc[mi][ni][2] + b0, acc[mi][ni][3] + b1));
            } else {
                if (n < LT) {
                    g_em[(size_t)m * LT + n]       = acc[mi][ni][0] + fcb[n];
                    g_em[(size_t)(m + 8) * LT + n] = acc[mi][ni][2] + fcb[n];
                }
                if (n + 1 < LT) {
                    g_em[(size_t)m * LT + n + 1]       = acc[mi][ni][1] + fcb[n + 1];
                    g_em[(size_t)(m + 8) * LT + n + 1] = acc[mi][ni][3] + fcb[n + 1];
                }
            }
        }
    }
}

// Persistent dual-chain LSTM: 64 CTAs, 8 channels each; warps 0-3 = fwd chain,
// warps 4-7 = bwd chain. Each chain: own named barrier, counter, SMEM buffers.
__global__ void __launch_bounds__(256, 1) k_lstm() {
    extern __shared__ char smem[];
    __nv_bfloat16* whh_s = (__nv_bfloat16*)smem;             // [2][32*520]
    __nv_bfloat16* hp_s  = whh_s + 2 * 32 * 520;             // [2][64*520]
    float* gates_s = (float*)(hp_s + 2 * 64 * 520);          // [2][64*34]

    int tid = threadIdx.x, lane = tid & 31, warp = tid >> 5;
    int dir = warp >> 2;                 // chain id
    int gwarp = warp & 3, gtid = tid & 127;
    int cta = blockIdx.x, c0 = cta * 8;
    int wm2 = gwarp & 1, wn2 = gwarp >> 1;

    __nv_bfloat16* whh = whh_s + dir * 32 * 520;
    __nv_bfloat16* hp  = hp_s  + dir * 64 * 520;
    float* gates = gates_s + dir * 64 * 34;

    // whole CTA loads both dirs' Whh gate-row slices
    for (int i = tid; i < 2 * 32 * 512; i += 256) {
        int d = i >> 14;
        int j = (i >> 9) & 31, k = i & 511;
        int r = ((j >> 3) << 9) + c0 + (j & 7);
        whh_s[d * 32 * 520 + j * 520 + k] = g_Whh[((size_t)d * NG + r) * HD + k];
    }
    __syncthreads();

    float c4[4] = {0.f, 0.f, 0.f, 0.f};
    int pb = gtid >> 1, q4 = (gtid & 1) * 4;     // batch row, channel quad
    const __nv_bfloat16* Gbase = g_G + (size_t)dir * MR * NG;
    int barid = 1 + dir;

    for (int s = 0; s < TLEN; s++) {
        int t = dir ? (TLEN - 1 - s) : s;
        const __nv_bfloat16* Gp = Gbase + ((size_t)t * 64 + pb) * NG + c0 + q4;
        uint2 rI = __ldg((const uint2*)Gp);
        uint2 rF = __ldg((const uint2*)(Gp + 512));
        uint2 rG = __ldg((const uint2*)(Gp + 1024));
        uint2 rO = __ldg((const uint2*)(Gp + 1536));

        if (s > 0) {
            if (gtid == 0) { while (ld_acq(&g_cnt[dir]) < s * 64) { } }
            bar_sync(barid, 128);
            int pt = dir ? t + 1 : t - 1;
            for (int i = gtid; i < 4096; i += 128) {
                int b = i >> 6, seg = i & 63;
                cp_async16(&hp[b * 520 + seg * 8],
                           g_H + ((size_t)dir * MR + (size_t)pt * 64 + b) * HD + seg * 8);
            }
            cp_commit(); cp_wait0();
            bar_sync(barid, 128);

            float c[2][2][4];
            #pragma unroll
            for (int mi = 0; mi < 2; mi++)
                #pragma unroll
                for (int f = 0; f < 2; f++)
                    #pragma unroll
                    for (int q = 0; q < 4; q++) c[mi][f][q] = 0.f;
            #pragma unroll 4
            for (int kk = 0; kk < 512; kk += 16) {
                int col = kk + (lane & 3) * 2;
                uint32_t a[2][4];
                #pragma unroll
                for (int mi = 0; mi < 2; mi++) {
                    int row = wm2 * 32 + mi * 16 + (lane >> 2);
                    a[mi][0] = *(const uint32_t*)&hp[row * 520 + col];
                    a[mi][1] = *(const uint32_t*)&hp[(row + 8) * 520 + col];
                    a[mi][2] = *(const uint32_t*)&hp[row * 520 + col + 8];
                    a[mi][3] = *(const uint32_t*)&hp[(row + 8) * 520 + col + 8];
                }
                #pragma unroll
                for (int f = 0; f < 2; f++) {
                    int n = wn2 * 16 + f * 8 + (lane >> 2);
                    uint32_t bb[2];
                    bb[0] = *(const uint32_t*)&whh[n * 520 + col];
                    bb[1] = *(const uint32_t*)&whh[n * 520 + col + 8];
                    #pragma unroll
                    for (int mi = 0; mi < 2; mi++) mma16816(c[mi][f], a[mi], bb);
                }
            }
            #pragma unroll
            for (int mi = 0; mi < 2; mi++)
                #pragma unroll
                for (int f = 0; f < 2; f++) {
                    int r0 = wm2 * 32 + mi * 16 + (lane >> 2);
                    int n  = wn2 * 16 + f * 8 + (lane & 3) * 2;
                    gates[r0 * 34 + n]           = c[mi][f][0];
                    gates[r0 * 34 + n + 1]       = c[mi][f][1];
                    gates[(r0 + 8) * 34 + n]     = c[mi][f][2];
                    gates[(r0 + 8) * 34 + n + 1] = c[mi][f][3];
                }
            bar_sync(barid, 128);
        }

        // pointwise: 4 channels per thread
        __nv_bfloat162 i01 = *(__nv_bfloat162*)&rI.x, i23 = *(__nv_bfloat162*)&rI.y;
        __nv_bfloat162 f01 = *(__nv_bfloat162*)&rF.x, f23 = *(__nv_bfloat162*)&rF.y;
        __nv_bfloat162 g01 = *(__nv_bfloat162*)&rG.x, g23 = *(__nv_bfloat162*)&rG.y;
        __nv_bfloat162 o01 = *(__nv_bfloat162*)&rO.x, o23 = *(__nv_bfloat162*)&rO.y;
        float gi[4] = {__bfloat162float(i01.x), __bfloat162float(i01.y),
                       __bfloat162float(i23.x), __bfloat162float(i23.y)};
        float gf[4] = {__bfloat162float(f01.x), __bfloat162float(f01.y),
                       __bfloat162float(f23.x), __bfloat162float(f23.y)};
        float gg[4] = {__bfloat162float(g01.x), __bfloat162float(g01.y),
                       __bfloat162float(g23.x), __bfloat162float(g23.y)};
        float go[4] = {__bfloat162float(o01.x), __bfloat162float(o01.y),
                       __bfloat162float(o23.x), __bfloat162float(o23.y)};
        if (s > 0) {
            const float* gr = &gates[pb * 34 + q4];
            #pragma unroll
            for (int u = 0; u < 4; u++) {
                gi[u] += gr[u];
                gf[u] += gr[u + 8];
                gg[u] += gr[u + 16];
                go[u] += gr[u + 24];
            }
        }
        __nv_bfloat162 hv[2];
        #pragma unroll
        for (int u = 0; u < 4; u++) {
            c4[u] = sig_f(gf[u]) * c4[u] + sig_f(gi[u]) * tanh_f(gg[u]);
        }
        hv[0] = __float22bfloat162_rn(make_float2(sig_f(go[0]) * tanh_f(c4[0]),
                                                  sig_f(go[1]) * tanh_f(c4[1])));
        hv[1] = __float22bfloat162_rn(make_float2(sig_f(go[2]) * tanh_f(c4[2]),
                                                  sig_f(go[3]) * tanh_f(c4[3])));
        *(uint2*)(g_H + ((size_t)dir * MR + (size_t)t * 64 + pb) * HD + c0 + q4) =
            *(const uint2*)hv;
        bar_sync(barid, 128);
        if (gtid == 0) { __threadfence(); red_add(&g_cnt[dir], 1); }
    }
}

__global__ void __launch_bounds__(256) k_crf(const float* strans, const float* etrans,
                                             const float* trans, const int* tags) {
    __shared__ float Et[48 * 49];
    __shared__ float alpha[48];
    __shared__ float p[48];
    __shared__ float part[4 * 48];
    __shared__ float red[256];
    __shared__ float sm_m;
    int b = blockIdx.x, tid = threadIdx.x;
    for (int i = tid; i < 2304; i += 256) {
        int r = i / 48, c = i - r * 48;
        Et[c * 49 + r] = __expf(trans[i]);
    }
    float num = 0.f;
    for (int t = tid; t < TLEN; t += 256) {
        int tg = tags[b * TLEN + t];
        num += g_em[((size_t)t * 64 + b) * LT + tg];
        num += (t > 0) ? trans[tags[b * TLEN + t - 1] * 48 + tg] : strans[tg];
        if (t == TLEN - 1) num += etrans[tg];
    }
    red[tid] = num; __syncthreads();
    for (int o = 128; o > 0; o >>= 1) { if (tid < o) red[tid] += red[tid + o]; __syncthreads(); }
    num = red[0];
    if (tid < 48) alpha[tid] = strans[tid] + g_em[(size_t)b * LT + tid];
    __syncthreads();
    for (int t = 1; t < TLEN; t++) {
        if (tid < 32) {
            float v = alpha[tid];
            if (tid < 16) v = fmaxf(v, alpha[tid + 32]);
            #pragma unroll
            for (int o = 16; o > 0; o >>= 1) v = fmaxf(v, __shfl_xor_sync(0xffffffffu, v, o));
            if (tid == 0) sm_m = v;
        }
        __syncthreads();
        if (tid < 48) p[tid] = __expf(alpha[tid] - sm_m);
        __syncthreads();
        int q = tid >> 6, j = tid & 63;
        if (j < 48) {
            float s = 0.f;
            #pragma unroll
            for (int u = 0; u < 12; u++) { int i = q * 12 + u; s += p[i] * Et[j * 49 + i]; }
            part[q * 48 + j] = s;
        }
        __syncthreads();
        if (tid < 48) {
            float s = part[tid] + part[48 + tid] + part[96 + tid] + part[144 + tid];
            alpha[tid] = g_em[((size_t)t * 64 + b) * LT + tid] + sm_m + __logf(s);
        }
        __syncthreads();
    }
    float v = (tid < 48) ? alpha[tid] + etrans[tid] : -1e30f;
    red[tid] = v; __syncthreads();
    for (int o = 128; o > 0; o >>= 1) { if (tid < o) red[tid] = fmaxf(red[tid], red[tid + o]); __syncthreads(); }
    float mx = red[0]; __syncthreads();
    red[tid] = (tid < 48) ? __expf(v - mx) : 0.f; __syncthreads();
    for (int o = 128; o > 0; o >>= 1) { if (tid < o) red[tid] += red[tid + o]; __syncthreads(); }
    if (tid == 0) g_llh[b] = num - (mx + __logf(red[0]));
}

__global__ void k_fin(float* out) {
    __shared__ float red[64];
    red[threadIdx.x] = g_llh[threadIdx.x]; __syncthreads();
    for (int o = 32; o > 0; o >>= 1) {
        if (threadIdx.x < o) red[threadIdx.x] += red[threadIdx.x + o];
        __syncthreads();
    }
    if (threadIdx.x == 0) out[0] = -red[0] / 64.f;
}

extern "C" void kernel_launch(void* const* d_in, const int* in_sizes, int n_in,
                              void* d_out, int out_size) {
    const float* emb    = (const float*)d_in[0];
    const float* wihf   = (const float*)d_in[1];
    const float* whhf   = (const float*)d_in[2];
    const float* bihf   = (const float*)d_in[3];
    const float* bhhf   = (const float*)d_in[4];
    const float* wihb   = (const float*)d_in[5];
    const float* whhb   = (const float*)d_in[6];
    const float* bihb   = (const float*)d_in[7];
    const float* bhhb   = (const float*)d_in[8];
    const float* fcw    = (const float*)d_in[9];
    const float* fcb    = (const float*)d_in[10];
    const float* strans = (const float*)d_in[11];
    const float* etrans = (const float*)d_in[12];
    const float* trans  = (const float*)d_in[13];
    const int*   x      = (const int*)d_in[14];
    const int*   tags   = (const int*)d_in[15];
    float* out = (float*)d_out;

    const int lstm_smem = 2 * 32 * 520 * 2 + 2 * 64 * 520 * 2 + 2 * 64 * 34 * 4;
    cudaFuncSetAttribute(k_lstm, cudaFuncAttributeMaxDynamicSharedMemorySize, lstm_smem);

    k_reset<<<1, 32>>>();
    k_prep<<<2048, 256>>>(wihf, whhf, bihf, bhhf, wihb, whhb, bihb, bhhb, fcw);
    k_gather<<<8192, 256>>>(emb, x);
    k_gemm<<<dim3(32, 256), 256>>>(0, fcb);
    k_lstm<<<64, 256, lstm_smem>>>();
    k_gemm<<<dim3(1, 256), 256>>>(1, fcb);
    k_crf<<<64, 256>>>(strans, etrans, trans, tags);
    k_fin<<<1, 64>>>(out);
}

// round 10
// speedup vs baseline: 1.2720x; 1.2720x over previous
#include <cuda_runtime.h>
#include <cuda_bf16.h>
#include <stdint.h>

#define TLEN  512
#define BATCH 64
#define EMBD  512
#define HD    512
#define NG    2048
#define LT    48
#define MR    (TLEN*BATCH)

__device__ __nv_bfloat16 g_A  [(size_t)MR*EMBD];
__device__ __nv_bfloat16 g_Wih[(size_t)2*NG*EMBD];
__device__ __nv_bfloat16 g_Whh[(size_t)2*NG*HD];
__device__ float         g_bias[2*NG];
__device__ __nv_bfloat16 g_fcw[(size_t)128*1024];
__device__ __nv_bfloat16 g_G  [(size_t)2*MR*NG];
__device__ __nv_bfloat16 g_H  [(size_t)2*MR*HD];
__device__ float         g_em [(size_t)MR*LT];
__device__ float         g_llh[BATCH];
__device__ int           g_cnt[2];

__device__ __forceinline__ void cp_async16(void* smem, const void* gmem) {
    uint32_t s = (uint32_t)__cvta_generic_to_shared(smem);
    asm volatile("cp.async.cg.shared.global [%0], [%1], 16;\n" :: "r"(s), "l"(gmem));
}
__device__ __forceinline__ void cp_commit() { asm volatile("cp.async.commit_group;\n"); }
__device__ __forceinline__ void cp_wait0()  { asm volatile("cp.async.wait_group 0;\n"); }
__device__ __forceinline__ void cp_wait1()  { asm volatile("cp.async.wait_group 1;\n"); }

__device__ __forceinline__ void ldm_x4(uint32_t* r, uint32_t saddr) {
    asm volatile("ldmatrix.sync.aligned.m8n8.x4.shared.b16 {%0,%1,%2,%3}, [%4];"
                 : "=r"(r[0]), "=r"(r[1]), "=r"(r[2]), "=r"(r[3]) : "r"(saddr));
}
__device__ __forceinline__ void mma16816(float* c, const uint32_t* a, const uint32_t* b) {
    asm volatile("mma.sync.aligned.m16n8k16.row.col.f32.bf16.bf16.f32 "
                 "{%0,%1,%2,%3},{%4,%5,%6,%7},{%8,%9},{%0,%1,%2,%3};\n"
                 : "+f"(c[0]), "+f"(c[1]), "+f"(c[2]), "+f"(c[3])
                 : "r"(a[0]), "r"(a[1]), "r"(a[2]), "r"(a[3]), "r"(b[0]), "r"(b[1]));
}
__device__ __forceinline__ float tanh_f(float x) {
    float y; asm("tanh.approx.f32 %0, %1;" : "=f"(y) : "f"(x)); return y;
}
__device__ __forceinline__ float sig_f(float x) { return 1.f / (1.f + __expf(-x)); }
__device__ __forceinline__ int ld_acq(const int* p) {
    int v; asm volatile("ld.acquire.gpu.global.b32 %0, [%1];" : "=r"(v) : "l"(p)); return v;
}
__device__ __forceinline__ void red_release(int* p, int v) {
    asm volatile("red.release.gpu.global.add.s32 [%0], %1;" :: "l"(p), "r"(v));
}

__global__ void k_reset() { if (threadIdx.x < 2) g_cnt[threadIdx.x] = 0; }

__global__ void k_prep(const float* wihf, const float* whhf, const float* bihf,
                       const float* bhhf, const float* wihb, const float* whhb,
                       const float* bihb, const float* bhhb, const float* fcw) {
    int id = blockIdx.x * blockDim.x + threadIdx.x;
    int st = gridDim.x * blockDim.x;
    const int NW = NG * EMBD;
    for (int i = id; i < NW; i += st) {
        g_Wih[i]      = __float2bfloat16(wihf[i]);
        g_Wih[NW + i] = __float2bfloat16(wihb[i]);
        g_Whh[i]      = __float2bfloat16(whhf[i]);
        g_Whh[NW + i] = __float2bfloat16(whhb[i]);
    }
    for (int i = id; i < NG; i += st) {
        g_bias[i]      = bihf[i] + bhhf[i];
        g_bias[NG + i] = bihb[i] + bhhb[i];
    }
    for (int i = id; i < 128 * 1024; i += st) {
        int l = i >> 10, k = i & 1023;
        g_fcw[i] = __float2bfloat16(l < LT ? fcw[l * 1024 + k] : 0.f);
    }
}

__global__ void k_gather(const float* emb, const int* x) {
    int id = blockIdx.x * 256 + threadIdx.x;
    int m = id >> 6, ch = id & 63;
    int t = m >> 6, b = m & 63;
    int tok = x[b * TLEN + t];
    const float4* s = (const float4*)(emb + (size_t)tok * EMBD + ch * 8);
    float4 u = s[0], v = s[1];
    __nv_bfloat162 pk[4];
    pk[0] = __float22bfloat162_rn(make_float2(u.x, u.y));
    pk[1] = __float22bfloat162_rn(make_float2(u.z, u.w));
    pk[2] = __float22bfloat162_rn(make_float2(v.x, v.y));
    pk[3] = __float22bfloat162_rn(make_float2(v.z, v.w));
    *(uint4*)(g_A + (size_t)m * EMBD + ch * 8) = *(const uint4*)pk;
}

// mode 0: G = A @ Wih^T + bias (bf16 out). mode 1: em = H @ fcw^T + fcb (fp32).
__global__ void __launch_bounds__(256, 2) k_gemm(int mode, const float* fcb) {
    __shared__ __nv_bfloat16 As[2][128 * 40];
    __shared__ __nv_bfloat16 Bs[2][128 * 40];
    int tid = threadIdx.x, lane = tid & 31, warp = tid >> 5;
    int wm = warp >> 2, wn = warp & 3;
    int m0 = blockIdx.y * 128, n0 = blockIdx.x * 128;
    int KC = mode ? 32 : 16;

    // ldmatrix lane address components (pitch 40 bf16)
    int ra = wm * 64 + (lane & 7) + ((lane >> 3) & 1) * 8;   // + mi*16
    int ca = (lane >> 4) * 8;                                // + kk
    int rb = wn * 32 + (lane & 7) + ((lane >> 4) & 1) * 8;   // + np*16
    int cb = ((lane >> 3) & 1) * 8;                          // + kk
    uint32_t sAb[2] = {(uint32_t)__cvta_generic_to_shared(&As[0][0]),
                       (uint32_t)__cvta_generic_to_shared(&As[1][0])};
    uint32_t sBb[2] = {(uint32_t)__cvta_generic_to_shared(&Bs[0][0]),
                       (uint32_t)__cvta_generic_to_shared(&Bs[1][0])};

    float acc[4][4][4];
    #pragma unroll
    for (int a = 0; a < 4; a++)
        #pragma unroll
        for (int b = 0; b < 4; b++)
            #pragma unroll
            for (int c = 0; c < 4; c++) acc[a][b][c] = 0.f;

    auto load_stage = [&](int kc, int s) {
        #pragma unroll
        for (int i = 0; i < 2; i++) {
            int c = tid + i * 256;
            int row = c >> 2, seg = c & 3;
            const __nv_bfloat16* sa;
            if (mode == 0)
                sa = g_A + (size_t)(m0 + row) * 512 + kc * 32 + seg * 8;
            else if (kc < 16)
                sa = g_H + (size_t)(m0 + row) * 512 + kc * 32 + seg * 8;
            else
                sa = g_H + (size_t)MR * HD + (size_t)(m0 + row) * 512 + (kc - 16) * 32 + seg * 8;
            cp_async16(&As[s][row * 40 + seg * 8], sa);
            const __nv_bfloat16* sb;
            if (mode == 0)
                sb = g_Wih + (size_t)(n0 + row) * 512 + kc * 32 + seg * 8;
            else
                sb = g_fcw + (size_t)(n0 + row) * 1024 + kc * 32 + seg * 8;
            cp_async16(&Bs[s][row * 40 + seg * 8], sb);
        }
    };

    load_stage(0, 0); cp_commit();
    for (int kc = 0; kc < KC; kc++) {
        int s = kc & 1;
        if (kc + 1 < KC) { load_stage(kc + 1, s ^ 1); cp_commit(); cp_wait1(); }
        else cp_wait0();
        __syncthreads();
        #pragma unroll
        for (int kk = 0; kk < 32; kk += 16) {
            uint32_t a[4][4], bq[2][4];
            #pragma unroll
            for (int mi = 0; mi < 4; mi++)
                ldm_x4(a[mi], sAb[s] + ((ra + mi * 16) * 40 + ca + kk) * 2);
            #pragma unroll
            for (int np = 0; np < 2; np++)
                ldm_x4(bq[np], sBb[s] + ((rb + np * 16) * 40 + cb + kk) * 2);
            #pragma unroll
            for (int mi = 0; mi < 4; mi++)
                #pragma unroll
                for (int ni = 0; ni < 4; ni++)
                    mma16816(acc[mi][ni], a[mi], &bq[ni >> 1][(ni & 1) * 2]);
        }
        __syncthreads();
    }

    #pragma unroll
    for (int mi = 0; mi < 4; mi++) {
        #pragma unroll
        for (int ni = 0; ni < 4; ni++) {
            int m = m0 + wm * 64 + mi * 16 + (lane >> 2);
            int n = n0 + wn * 32 + ni * 8 + (lane & 3) * 2;
            if (mode == 0) {
                int dir = n >> 11, r = n & 2047;
                size_t o1 = ((size_t)dir * MR + m) * NG + r;
                size_t o2 = ((size_t)dir * MR + m + 8) * NG + r;
                float b0 = g_bias[n], b1 = g_bias[n + 1];
                *(__nv_bfloat162*)&g_G[o1] = __float22bfloat162_rn(
                    make_float2(acc[mi][ni][0] + b0, acc[mi][ni][1] + b1));
                *(__nv_bfloat162*)&g_G[o2] = __float22bfloat162_rn(
                    make_float2(acc[mi][ni][2] + b0, acc[mi][ni][3] + b1));
            } else {
                if (n < LT) {
                    g_em[(size_t)m * LT + n]       = acc[mi][ni][0] + fcb[n];
                    g_em[(size_t)(m + 8) * LT + n] = acc[mi][ni][2] + fcb[n];
                }
                if (n + 1 < LT) {
                    g_em[(size_t)m * LT + n + 1]       = acc[mi][ni][1] + fcb[n + 1];
                    g_em[(size_t)(m + 8) * LT + n + 1] = acc[mi][ni][3] + fcb[n + 1];
                }
            }
        }
    }
}

// Persistent LSTM: 128 CTAs (dir=blk>>6), 8 channels each; 8-warp ldmatrix MMA.
__global__ void __launch_bounds__(256, 1) k_lstm() {
    extern __shared__ char smem[];
    __nv_bfloat16* whh_s = (__nv_bfloat16*)smem;           // 32 x 520
    __nv_bfloat16* hp_s  = whh_s + 32 * 520;               // 64 x 520
    float* gates_s = (float*)(hp_s + 64 * 520);            // 64 x 34

    int tid = threadIdx.x, lane = tid & 31, warp = tid >> 5;
    int dir = blockIdx.x >> 6, cta = blockIdx.x & 63, c0 = cta * 8;
    int wm = warp & 3, wn = warp >> 2;

    for (int i = tid; i < 32 * 512; i += 256) {
        int j = i >> 9, k = i & 511;
        int r = ((j >> 3) << 9) + c0 + (j & 7);
        whh_s[j * 520 + k] = g_Whh[((size_t)dir * NG + r) * HD + k];
    }
    __syncthreads();

    // ldmatrix lane addresses (pitch 520)
    uint32_t hpB  = (uint32_t)__cvta_generic_to_shared(hp_s);
    uint32_t whhB = (uint32_t)__cvta_generic_to_shared(whh_s);
    int ra = wm * 16 + (lane & 7) + ((lane >> 3) & 1) * 8;
    int ca = (lane >> 4) * 8;
    int rb = wn * 16 + (lane & 7) + ((lane >> 4) & 1) * 8;
    int cb = ((lane >> 3) & 1) * 8;
    uint32_t aAddr = hpB  + (ra * 520 + ca) * 2;
    uint32_t bAddr = whhB + (rb * 520 + cb) * 2;

    float2 creg = make_float2(0.f, 0.f);
    int pb = tid >> 2, pc = (tid & 3) * 2;
    const __nv_bfloat16* Gbase = g_G + (size_t)dir * MR * NG;

    for (int s = 0; s < TLEN; s++) {
        int t = dir ? (TLEN - 1 - s) : s;
        const __nv_bfloat16* Gp = Gbase + ((size_t)t * 64 + pb) * NG + c0 + pc;
        __nv_bfloat162 gI = __ldg((const __nv_bfloat162*)Gp);
        __nv_bfloat162 gF = __ldg((const __nv_bfloat162*)(Gp + 512));
        __nv_bfloat162 gG = __ldg((const __nv_bfloat162*)(Gp + 1024));
        __nv_bfloat162 gO = __ldg((const __nv_bfloat162*)(Gp + 1536));

        if (s > 0) {
            if (tid == 0) { while (ld_acq(&g_cnt[dir]) < s * 64) { } }
            __syncthreads();
            int pt = dir ? t + 1 : t - 1;
            for (int i = tid; i < 4096; i += 256) {
                int b = i >> 6, seg = i & 63;
                cp_async16(&hp_s[b * 520 + seg * 8],
                           g_H + ((size_t)dir * MR + (size_t)pt * 64 + b) * HD + seg * 8);
            }
            cp_commit(); cp_wait0();
            __syncthreads();

            float c[2][4] = {{0, 0, 0, 0}, {0, 0, 0, 0}};
            #pragma unroll 8
            for (int kk = 0; kk < 512; kk += 16) {
                uint32_t a[4], bfr[4];
                ldm_x4(a,   aAddr + kk * 2);
                ldm_x4(bfr, bAddr + kk * 2);
                mma16816(c[0], a, bfr);
                mma16816(c[1], a, bfr + 2);
            }
            #pragma unroll
            for (int f = 0; f < 2; f++) {
                int r0 = wm * 16 + (lane >> 2);
                int n  = wn * 16 + f * 8 + (lane & 3) * 2;
                gates_s[r0 * 34 + n]           = c[f][0];
                gates_s[r0 * 34 + n + 1]       = c[f][1];
                gates_s[(r0 + 8) * 34 + n]     = c[f][2];
                gates_s[(r0 + 8) * 34 + n + 1] = c[f][3];
            }
            __syncthreads();
        }

        float aI0 = 0, aI1 = 0, aF0 = 0, aF1 = 0, aG0 = 0, aG1 = 0, aO0 = 0, aO1 = 0;
        if (s > 0) {
            const float* gr = &gates_s[pb * 34];
            aI0 = gr[pc];      aI1 = gr[pc + 1];
            aF0 = gr[pc + 8];  aF1 = gr[pc + 9];
            aG0 = gr[pc + 16]; aG1 = gr[pc + 17];
            aO0 = gr[pc + 24]; aO1 = gr[pc + 25];
        }
        creg.x = sig_f(__bfloat162float(gF.x) + aF0) * creg.x +
                 sig_f(__bfloat162float(gI.x) + aI0) * tanh_f(__bfloat162float(gG.x) + aG0);
        creg.y = sig_f(__bfloat162float(gF.y) + aF1) * creg.y +
                 sig_f(__bfloat162float(gI.y) + aI1) * tanh_f(__bfloat162float(gG.y) + aG1);
        float h0 = sig_f(__bfloat162float(gO.x) + aO0) * tanh_f(creg.x);
        float h1 = sig_f(__bfloat162float(gO.y) + aO1) * tanh_f(creg.y);
        *(__nv_bfloat162*)(g_H + ((size_t)dir * MR + (size_t)t * 64 + pb) * HD + c0 + pc) =
            __float22bfloat162_rn(make_float2(h0, h1));
        __syncthreads();
        if (tid == 0) red_release(&g_cnt[dir], 1);
    }
}

// CRF: 64 CTAs x 64 threads; thread j owns tag j; exp(trans) column in registers;
// incremental shift (alpha-hat[0] == 0) removes the per-step max reduction.
__global__ void __launch_bounds__(64) k_crf(const float* strans, const float* etrans,
                                            const float* trans, const int* tags) {
    __shared__ float p_s[48];
    __shared__ float v0_s;
    __shared__ float red[64];
    int b = blockIdx.x, tid = threadIdx.x;
    bool act = tid < LT;

    float Et[48];
    if (act) {
        #pragma unroll 8
        for (int i = 0; i < 48; i++) Et[i] = __expf(trans[i * 48 + tid]);
    }
    // numerator (mask all-ones since x>0)
    float num = 0.f;
    for (int t = tid; t < TLEN; t += 64) {
        int tg = tags[b * TLEN + t];
        num += g_em[((size_t)t * 64 + b) * LT + tg];
        num += (t > 0) ? trans[tags[b * TLEN + t - 1] * 48 + tg] : strans[tg];
        if (t == TLEN - 1) num += etrans[tg];
    }
    red[tid] = num; __syncthreads();
    for (int o = 32; o > 0; o >>= 1) { if (tid < o) red[tid] += red[tid + o]; __syncthreads(); }
    num = red[0];
    __syncthreads();

    float ah = 0.f, S = 0.f;
    {
        float a0 = act ? (strans[tid] + g_em[(size_t)b * LT + tid]) : 0.f;
        if (tid == 0) v0_s = a0;
        __syncthreads();
        S = v0_s;
        ah = a0 - v0_s;
        __syncthreads();
    }
    for (int t = 1; t < TLEN; t++) {
        float e = act ? g_em[((size_t)t * 64 + b) * LT + tid] : 0.f;
        if (act) p_s[tid] = __expf(ah);
        __syncthreads();
        float v = 0.f;
        if (act) {
            float dot = 0.f;
            #pragma unroll 12
            for (int i = 0; i < 48; i++) dot += p_s[i] * Et[i];
            v = e + __logf(dot);
            if (tid == 0) v0_s = v;
        }
        __syncthreads();
        ah = v - v0_s;
        S += v0_s;
    }
    float fv = act ? (ah + etrans[tid]) : -1e30f;
    red[tid] = fv; __syncthreads();
    for (int o = 32; o > 0; o >>= 1) { if (tid < o) red[tid] = fmaxf(red[tid], red[tid + o]); __syncthreads(); }
    float mx = red[0]; __syncthreads();
    red[tid] = act ? __expf(fv - mx) : 0.f; __syncthreads();
    for (int o = 32; o > 0; o >>= 1) { if (tid < o) red[tid] += red[tid + o]; __syncthreads(); }
    if (tid == 0) g_llh[b] = num - (S + mx + __logf(red[0]));
}

__global__ void k_fin(float* out) {
    __shared__ float red[64];
    red[threadIdx.x] = g_llh[threadIdx.x]; __syncthreads();
    for (int o = 32; o > 0; o >>= 1) {
        if (threadIdx.x < o) red[threadIdx.x] += red[threadIdx.x + o];
        __syncthreads();
    }
    if (threadIdx.x == 0) out[0] = -red[0] / 64.f;
}

extern "C" void kernel_launch(void* const* d_in, const int* in_sizes, int n_in,
                              void* d_out, int out_size) {
    const float* emb    = (const float*)d_in[0];
    const float* wihf   = (const float*)d_in[1];
    const float* whhf   = (const float*)d_in[2];
    const float* bihf   = (const float*)d_in[3];
    const float* bhhf   = (const float*)d_in[4];
    const float* wihb   = (const float*)d_in[5];
    const float* whhb   = (const float*)d_in[6];
    const float* bihb   = (const float*)d_in[7];
    const float* bhhb   = (const float*)d_in[8];
    const float* fcw    = (const float*)d_in[9];
    const float* fcb    = (const float*)d_in[10];
    const float* strans = (const float*)d_in[11];
    const float* etrans = (const float*)d_in[12];
    const float* trans  = (const float*)d_in[13];
    const int*   x      = (const int*)d_in[14];
    const int*   tags   = (const int*)d_in[15];
    float* out = (float*)d_out;

    const int lstm_smem = 32 * 520 * 2 + 64 * 520 * 2 + 64 * 34 * 4;
    cudaFuncSetAttribute(k_lstm, cudaFuncAttributeMaxDynamicSharedMemorySize, lstm_smem);

    k_reset<<<1, 32>>>();
    k_prep<<<2048, 256>>>(wihf, whhf, bihf, bhhf, wihb, whhb, bihb, bhhb, fcw);
    k_gather<<<8192, 256>>>(emb, x);
    k_gemm<<<dim3(32, 256), 256>>>(0, fcb);
    k_lstm<<<128, 256, lstm_smem>>>();
    k_gemm<<<dim3(1, 256), 256>>>(1, fcb);
    k_crf<<<64, 64>>>(strans, etrans, trans, tags);
    k_fin<<<1, 64>>>(out);
}

// round 11
// speedup vs baseline: 1.3599x; 1.0691x over previous
#include <cuda_runtime.h>
#include <cuda_bf16.h>
#include <stdint.h>

#define TLEN  512
#define BATCH 64
#define EMBD  512
#define HD    512
#define NG    2048
#define LT    48
#define MR    (TLEN*BATCH)

__device__ __nv_bfloat16 g_A  [(size_t)MR*EMBD];
__device__ __nv_bfloat16 g_Wih[(size_t)2*NG*EMBD];
__device__ __nv_bfloat16 g_Whh[(size_t)2*NG*HD];
__device__ float         g_bias[2*NG];
__device__ __nv_bfloat16 g_fcw[(size_t)128*1024];
__device__ __nv_bfloat16 g_G  [(size_t)2*MR*NG];   // interleaved: [..][m][C*4+gate]
__device__ __nv_bfloat16 g_H  [(size_t)2*MR*HD];
__device__ float         g_em [(size_t)MR*LT];
__device__ float         g_llh[BATCH];
__device__ int           g_cnt[2];

__device__ __forceinline__ void cp_async16(void* smem, const void* gmem) {
    uint32_t s = (uint32_t)__cvta_generic_to_shared(smem);
    asm volatile("cp.async.cg.shared.global [%0], [%1], 16;\n" :: "r"(s), "l"(gmem));
}
__device__ __forceinline__ void cp_commit() { asm volatile("cp.async.commit_group;\n"); }
__device__ __forceinline__ void cp_wait0()  { asm volatile("cp.async.wait_group 0;\n"); }
__device__ __forceinline__ void cp_wait1()  { asm volatile("cp.async.wait_group 1;\n"); }

__device__ __forceinline__ void ldm_x4(uint32_t* r, uint32_t saddr) {
    asm volatile("ldmatrix.sync.aligned.m8n8.x4.shared.b16 {%0,%1,%2,%3}, [%4];"
                 : "=r"(r[0]), "=r"(r[1]), "=r"(r[2]), "=r"(r[3]) : "r"(saddr));
}
__device__ __forceinline__ void mma16816(float* c, const uint32_t* a, const uint32_t* b) {
    asm volatile("mma.sync.aligned.m16n8k16.row.col.f32.bf16.bf16.f32 "
                 "{%0,%1,%2,%3},{%4,%5,%6,%7},{%8,%9},{%0,%1,%2,%3};\n"
                 : "+f"(c[0]), "+f"(c[1]), "+f"(c[2]), "+f"(c[3])
                 : "r"(a[0]), "r"(a[1]), "r"(a[2]), "r"(a[3]), "r"(b[0]), "r"(b[1]));
}
__device__ __forceinline__ float tanh_f(float x) {
    float y; asm("tanh.approx.f32 %0, %1;" : "=f"(y) : "f"(x)); return y;
}
__device__ __forceinline__ float sig_f(float x) { return 1.f / (1.f + __expf(-x)); }
__device__ __forceinline__ int ld_acq(const int* p) {
    int v; asm volatile("ld.acquire.gpu.global.b32 %0, [%1];" : "=r"(v) : "l"(p)); return v;
}
__device__ __forceinline__ void red_release(int* p, int v) {
    asm volatile("red.release.gpu.global.add.s32 [%0], %1;" :: "l"(p), "r"(v));
}

__global__ void k_reset() { if (threadIdx.x < 2) g_cnt[threadIdx.x] = 0; }

__global__ void k_prep(const float* wihf, const float* whhf, const float* bihf,
                       const float* bhhf, const float* wihb, const float* whhb,
                       const float* bihb, const float* bhhb, const float* fcw) {
    int id = blockIdx.x * blockDim.x + threadIdx.x;
    int st = gridDim.x * blockDim.x;
    const int NW = NG * EMBD;
    for (int i = id; i < NW; i += st) {
        g_Wih[i]      = __float2bfloat16(wihf[i]);
        g_Wih[NW + i] = __float2bfloat16(wihb[i]);
        g_Whh[i]      = __float2bfloat16(whhf[i]);
        g_Whh[NW + i] = __float2bfloat16(whhb[i]);
    }
    for (int i = id; i < NG; i += st) {
        g_bias[i]      = bihf[i] + bhhf[i];
        g_bias[NG + i] = bihb[i] + bhhb[i];
    }
    for (int i = id; i < 128 * 1024; i += st) {
        int l = i >> 10, k = i & 1023;
        g_fcw[i] = __float2bfloat16(l < LT ? fcw[l * 1024 + k] : 0.f);
    }
}

__global__ void k_gather(const float* emb, const int* x) {
    int id = blockIdx.x * 256 + threadIdx.x;
    int m = id >> 6, ch = id & 63;
    int t = m >> 6, b = m & 63;
    int tok = x[b * TLEN + t];
    const float4* s = (const float4*)(emb + (size_t)tok * EMBD + ch * 8);
    float4 u = s[0], v = s[1];
    __nv_bfloat162 pk[4];
    pk[0] = __float22bfloat162_rn(make_float2(u.x, u.y));
    pk[1] = __float22bfloat162_rn(make_float2(u.z, u.w));
    pk[2] = __float22bfloat162_rn(make_float2(v.x, v.y));
    pk[3] = __float22bfloat162_rn(make_float2(v.z, v.w));
    *(uint4*)(g_A + (size_t)m * EMBD + ch * 8) = *(const uint4*)pk;
}

// mode 0: G = A @ Wih^T + bias -> bf16, stored interleaved [m][C*4+gate].
// mode 1: em = H @ fcw^T + fcb (fp32).
__global__ void __launch_bounds__(256, 2) k_gemm(int mode, const float* fcb) {
    __shared__ __nv_bfloat16 As[2][128 * 40];
    __shared__ __nv_bfloat16 Bs[2][128 * 40];
    int tid = threadIdx.x, lane = tid & 31, warp = tid >> 5;
    int wm = warp >> 2, wn = warp & 3;
    int m0 = blockIdx.y * 128, n0 = blockIdx.x * 128;
    int KC = mode ? 32 : 16;

    int ra = wm * 64 + (lane & 7) + ((lane >> 3) & 1) * 8;
    int ca = (lane >> 4) * 8;
    int rb = wn * 32 + (lane & 7) + ((lane >> 4) & 1) * 8;
    int cb = ((lane >> 3) & 1) * 8;
    uint32_t sAb[2] = {(uint32_t)__cvta_generic_to_shared(&As[0][0]),
                       (uint32_t)__cvta_generic_to_shared(&As[1][0])};
    uint32_t sBb[2] = {(uint32_t)__cvta_generic_to_shared(&Bs[0][0]),
                       (uint32_t)__cvta_generic_to_shared(&Bs[1][0])};

    float acc[4][4][4];
    #pragma unroll
    for (int a = 0; a < 4; a++)
        #pragma unroll
        for (int b = 0; b < 4; b++)
            #pragma unroll
            for (int c = 0; c < 4; c++) acc[a][b][c] = 0.f;

    auto load_stage = [&](int kc, int s) {
        #pragma unroll
        for (int i = 0; i < 2; i++) {
            int c = tid + i * 256;
            int row = c >> 2, seg = c & 3;
            const __nv_bfloat16* sa;
            if (mode == 0)
                sa = g_A + (size_t)(m0 + row) * 512 + kc * 32 + seg * 8;
            else if (kc < 16)
                sa = g_H + (size_t)(m0 + row) * 512 + kc * 32 + seg * 8;
            else
                sa = g_H + (size_t)MR * HD + (size_t)(m0 + row) * 512 + (kc - 16) * 32 + seg * 8;
            cp_async16(&As[s][row * 40 + seg * 8], sa);
            const __nv_bfloat16* sb;
            if (mode == 0)
                sb = g_Wih + (size_t)(n0 + row) * 512 + kc * 32 + seg * 8;
            else
                sb = g_fcw + (size_t)(n0 + row) * 1024 + kc * 32 + seg * 8;
            cp_async16(&Bs[s][row * 40 + seg * 8], sb);
        }
    };

    load_stage(0, 0); cp_commit();
    for (int kc = 0; kc < KC; kc++) {
        int s = kc & 1;
        if (kc + 1 < KC) { load_stage(kc + 1, s ^ 1); cp_commit(); cp_wait1(); }
        else cp_wait0();
        __syncthreads();
        #pragma unroll
        for (int kk = 0; kk < 32; kk += 16) {
            uint32_t a[4][4], bq[2][4];
            #pragma unroll
            for (int mi = 0; mi < 4; mi++)
                ldm_x4(a[mi], sAb[s] + ((ra + mi * 16) * 40 + ca + kk) * 2);
            #pragma unroll
            for (int np = 0; np < 2; np++)
                ldm_x4(bq[np], sBb[s] + ((rb + np * 16) * 40 + cb + kk) * 2);
            #pragma unroll
            for (int mi = 0; mi < 4; mi++)
                #pragma unroll
                for (int ni = 0; ni < 4; ni++)
                    mma16816(acc[mi][ni], a[mi], &bq[ni >> 1][(ni & 1) * 2]);
        }
        __syncthreads();
    }

    #pragma unroll
    for (int mi = 0; mi < 4; mi++) {
        #pragma unroll
        for (int ni = 0; ni < 4; ni++) {
            int m = m0 + wm * 64 + mi * 16 + (lane >> 2);
            int n = n0 + wn * 32 + ni * 8 + (lane & 3) * 2;
            if (mode == 0) {
                #pragma unroll
                for (int u = 0; u < 2; u++) {       // n and n+1
                    int nn = n + u;
                    int dirn = nn >> 11, r = nn & 2047;
                    int gate = r >> 9, C = r & 511;
                    float bz = g_bias[nn];
                    size_t base = ((size_t)dirn * MR + m) * 2048 + (size_t)C * 4 + gate;
                    g_G[base]            = __float2bfloat16(acc[mi][ni][u] + bz);
                    g_G[base + 8 * 2048] = __float2bfloat16(acc[mi][ni][u + 2] + bz);
                }
            } else {
                if (n < LT) {
                    g_em[(size_t)m * LT + n]       = acc[mi][ni][0] + fcb[n];
                    g_em[(size_t)(m + 8) * LT + n] = acc[mi][ni][2] + fcb[n];
                }
                if (n + 1 < LT) {
                    g_em[(size_t)m * LT + n + 1]       = acc[mi][ni][1] + fcb[n + 1];
                    g_em[(size_t)(m + 8) * LT + n + 1] = acc[mi][ni][3] + fcb[n + 1];
                }
            }
        }
    }
}

// Persistent LSTM: 128 CTAs (dir=blk>>6), 8 channels each.
// Gate columns interleaved so MMA fragments feed the pointwise directly.
// Column j (0..31) holds weight row gate(j)*512 + c0 + ch(j):
//   gate(j) = (j&1) | ((j>>3)&1)<<1 ; ch(j) = (j>>4)*4 + ((j&7)>>1)
__global__ void __launch_bounds__(256, 1) k_lstm() {
    extern __shared__ char smem[];
    __nv_bfloat16* whh_s = (__nv_bfloat16*)smem;           // 32 x 520
    __nv_bfloat16* hp_s  = whh_s + 32 * 520;               // 64 x 520

    int tid = threadIdx.x, lane = tid & 31, warp = tid >> 5;
    int dir = blockIdx.x >> 6, cta = blockIdx.x & 63, c0 = cta * 8;
    int wm = warp & 3, wn = warp >> 2;

    for (int i = tid; i < 32 * 512; i += 256) {
        int j = i >> 9, k = i & 511;
        int gate = (j & 1) | (((j >> 3) & 1) << 1);
        int ch   = ((j >> 4) << 2) | ((j & 7) >> 1);
        int r = (gate << 9) + c0 + ch;
        whh_s[j * 520 + k] = g_Whh[((size_t)dir * NG + r) * HD + k];
    }
    __syncthreads();

    uint32_t hpB  = (uint32_t)__cvta_generic_to_shared(hp_s);
    uint32_t whhB = (uint32_t)__cvta_generic_to_shared(whh_s);
    int ra = wm * 16 + (lane & 7) + ((lane >> 3) & 1) * 8;
    int ca = (lane >> 4) * 8;
    int rb = wn * 16 + (lane & 7) + ((lane >> 4) & 1) * 8;
    int cb = ((lane >> 3) & 1) * 8;
    uint32_t aAddr = hpB  + (ra * 520 + ca) * 2;
    uint32_t bAddr = whhB + (rb * 520 + cb) * 2;

    int r0  = wm * 16 + (lane >> 2);              // batch rows r0, r0+8
    int chg = c0 + wn * 4 + (lane & 3);           // this thread's channel
    float cs0 = 0.f, cs1 = 0.f;                   // c-state
    const __nv_bfloat16* Gbase = g_G + (size_t)dir * MR * NG;

    for (int s = 0; s < TLEN; s++) {
        int t = dir ? (TLEN - 1 - s) : s;
        const __nv_bfloat16* Gp = Gbase + ((size_t)t * 64 + r0) * 2048 + chg * 4;
        uint2 gA = __ldg((const uint2*)Gp);               // (i,f,g,o) row r0
        uint2 gB = __ldg((const uint2*)(Gp + 8 * 2048));  // row r0+8

        float c[2][4] = {{0, 0, 0, 0}, {0, 0, 0, 0}};
        if (s > 0) {
            if (tid == 0) { while (ld_acq(&g_cnt[dir]) < s * 64) { } }
            __syncthreads();
            int pt = dir ? t + 1 : t - 1;
            const __nv_bfloat16* Hs = g_H + ((size_t)dir * MR + (size_t)pt * 64) * HD;
            for (int i = tid; i < 2048; i += 256) {          // k 0..255
                int b = i >> 5, seg = i & 31;
                cp_async16(&hp_s[b * 520 + seg * 8], Hs + (size_t)b * 512 + seg * 8);
            }
            cp_commit();
            for (int i = tid; i < 2048; i += 256) {          // k 256..511
                int b = i >> 5, seg = i & 31;
                cp_async16(&hp_s[b * 520 + 256 + seg * 8], Hs + (size_t)b * 512 + 256 + seg * 8);
            }
            cp_commit();
            cp_wait1();
            __syncthreads();
            #pragma unroll 4
            for (int kk = 0; kk < 256; kk += 16) {
                uint32_t a[4], bfr[4];
                ldm_x4(a,   aAddr + kk * 2);
                ldm_x4(bfr, bAddr + kk * 2);
                mma16816(c[0], a, bfr);
                mma16816(c[1], a, bfr + 2);
            }
            cp_wait0();
            __syncthreads();
            #pragma unroll 4
            for (int kk = 256; kk < 512; kk += 16) {
                uint32_t a[4], bfr[4];
                ldm_x4(a,   aAddr + kk * 2);
                ldm_x4(bfr, bAddr + kk * 2);
                mma16816(c[0], a, bfr);
                mma16816(c[1], a, bfr + 2);
            }
        }

        // pointwise straight from fragments: c[0]={i,f}, c[1]={g,o}; [2],[3] = row+8
        __nv_bfloat162 if0 = *(__nv_bfloat162*)&gA.x;
        __nv_bfloat162 go0 = *(__nv_bfloat162*)&gA.y;
        __nv_bfloat162 if1 = *(__nv_bfloat162*)&gB.x;
        __nv_bfloat162 go1 = *(__nv_bfloat162*)&gB.y;
        float i0 = __bfloat162float(if0.x) + c[0][0];
        float f0 = __bfloat162float(if0.y) + c[0][1];
        float g0 = __bfloat162float(go0.x) + c[1][0];
        float o0 = __bfloat162float(go0.y) + c[1][1];
        float i1 = __bfloat162float(if1.x) + c[0][2];
        float f1 = __bfloat162float(if1.y) + c[0][3];
        float g1 = __bfloat162float(go1.x) + c[1][2];
        float o1 = __bfloat162float(go1.y) + c[1][3];
        cs0 = sig_f(f0) * cs0 + sig_f(i0) * tanh_f(g0);
        cs1 = sig_f(f1) * cs1 + sig_f(i1) * tanh_f(g1);
        float h0 = sig_f(o0) * tanh_f(cs0);
        float h1 = sig_f(o1) * tanh_f(cs1);
        __nv_bfloat16* Hd = g_H + ((size_t)dir * MR + (size_t)t * 64 + r0) * HD + chg;
        Hd[0]        = __float2bfloat16(h0);
        Hd[8 * 512]  = __float2bfloat16(h1);
        __syncthreads();
        if (tid == 0) red_release(&g_cnt[dir], 1);
    }
}

// CRF: 64 CTAs x 64 threads; thread j owns tag j; exp(trans) column in registers;
// incremental shift removes the per-step max reduction.
__global__ void __launch_bounds__(64) k_crf(const float* strans, const float* etrans,
                                            const float* trans, const int* tags) {
    __shared__ float p_s[48];
    __shared__ float v0_s;
    __shared__ float red[64];
    int b = blockIdx.x, tid = threadIdx.x;
    bool act = tid < LT;

    float Et[48];
    if (act) {
        #pragma unroll 8
        for (int i = 0; i < 48; i++) Et[i] = __expf(trans[i * 48 + tid]);
    }
    float num = 0.f;
    for (int t = tid; t < TLEN; t += 64) {
        int tg = tags[b * TLEN + t];
        num += g_em[((size_t)t * 64 + b) * LT + tg];
        num += (t > 0) ? trans[tags[b * TLEN + t - 1] * 48 + tg] : strans[tg];
        if (t == TLEN - 1) num += etrans[tg];
    }
    red[tid] = num; __syncthreads();
    for (int o = 32; o > 0; o >>= 1) { if (tid < o) red[tid] += red[tid + o]; __syncthreads(); }
    num = red[0];
    __syncthreads();

    float ah = 0.f, S = 0.f;
    {
        float a0 = act ? (strans[tid] + g_em[(size_t)b * LT + tid]) : 0.f;
        if (tid == 0) v0_s = a0;
        __syncthreads();
        S = v0_s;
        ah = a0 - v0_s;
        __syncthreads();
    }
    for (int t = 1; t < TLEN; t++) {
        float e = act ? g_em[((size_t)t * 64 + b) * LT + tid] : 0.f;
        if (act) p_s[tid] = __expf(ah);
        __syncthreads();
        float v = 0.f;
        if (act) {
            float dot = 0.f;
            #pragma unroll 12
            for (int i = 0; i < 48; i++) dot += p_s[i] * Et[i];
            v = e + __logf(dot);
            if (tid == 0) v0_s = v;
        }
        __syncthreads();
        ah = v - v0_s;
        S += v0_s;
    }
    float fv = act ? (ah + etrans[tid]) : -1e30f;
    red[tid] = fv; __syncthreads();
    for (int o = 32; o > 0; o >>= 1) { if (tid < o) red[tid] = fmaxf(red[tid], red[tid + o]); __syncthreads(); }
    float mx = red[0]; __syncthreads();
    red[tid] = act ? __expf(fv - mx) : 0.f; __syncthreads();
    for (int o = 32; o > 0; o >>= 1) { if (tid < o) red[tid] += red[tid + o]; __syncthreads(); }
    if (tid == 0) g_llh[b] = num - (S + mx + __logf(red[0]));
}

__global__ void k_fin(float* out) {
    __shared__ float red[64];
    red[threadIdx.x] = g_llh[threadIdx.x]; __syncthreads();
    for (int o = 32; o > 0; o >>= 1) {
        if (threadIdx.x < o) red[threadIdx.x] += red[threadIdx.x + o];
        __syncthreads();
    }
    if (threadIdx.x == 0) out[0] = -red[0] / 64.f;
}

extern "C" void kernel_launch(void* const* d_in, const int* in_sizes, int n_in,
                              void* d_out, int out_size) {
    const float* emb    = (const float*)d_in[0];
    const float* wihf   = (const float*)d_in[1];
    const float* whhf   = (const float*)d_in[2];
    const float* bihf   = (const float*)d_in[3];
    const float* bhhf   = (const float*)d_in[4];
    const float* wihb   = (const float*)d_in[5];
    const float* whhb   = (const float*)d_in[6];
    const float* bihb   = (const float*)d_in[7];
    const float* bhhb   = (const float*)d_in[8];
    const float* fcw    = (const float*)d_in[9];
    const float* fcb    = (const float*)d_in[10];
    const float* strans = (const float*)d_in[11];
    const float* etrans = (const float*)d_in[12];
    const float* trans  = (const float*)d_in[13];
    const int*   x      = (const int*)d_in[14];
    const int*   tags   = (const int*)d_in[15];
    float* out = (float*)d_out;

    const int lstm_smem = 32 * 520 * 2 + 64 * 520 * 2;
    cudaFuncSetAttribute(k_lstm, cudaFuncAttributeMaxDynamicSharedMemorySize, lstm_smem);

    k_reset<<<1, 32>>>();
    k_prep<<<2048, 256>>>(wihf, whhf, bihf, bhhf, wihb, whhb, bihb, bhhb, fcw);
    k_gather<<<8192, 256>>>(emb, x);
    k_gemm<<<dim3(32, 256), 256>>>(0, fcb);
    k_lstm<<<128, 256, lstm_smem>>>();
    k_gemm<<<dim3(1, 256), 256>>>(1, fcb);
    k_crf<<<64, 64>>>(strans, etrans, trans, tags);
    k_fin<<<1, 64>>>(out);
}

// round 12
// speedup vs baseline: 1.5032x; 1.1054x over previous
#include <cuda_runtime.h>
#include <cuda_bf16.h>
#include <stdint.h>

#define TLEN  512
#define BATCH 64
#define EMBD  512
#define HD    512
#define NG    2048
#define LT    48
#define MR    (TLEN*BATCH)

__device__ __nv_bfloat16 g_A  [(size_t)MR*EMBD];
__device__ __nv_bfloat16 g_Wih[(size_t)2*NG*EMBD];
__device__ __nv_bfloat16 g_Whh[(size_t)2*NG*HD];
__device__ float         g_bias[2*NG];
__device__ __nv_bfloat16 g_fcw[(size_t)128*1024];
__device__ __nv_bfloat16 g_G  [(size_t)2*MR*NG];   // gate-major: [dir][m][gate*512+C]
__device__ __nv_bfloat16 g_H  [(size_t)2*MR*HD];
__device__ float         g_em [(size_t)MR*LT];
__device__ float         g_llh[BATCH];
__device__ int           g_cnt[2];

__device__ __forceinline__ void cp_async16(void* smem, const void* gmem) {
    uint32_t s = (uint32_t)__cvta_generic_to_shared(smem);
    asm volatile("cp.async.cg.shared.global [%0], [%1], 16;\n" :: "r"(s), "l"(gmem));
}
__device__ __forceinline__ void cp_commit() { asm volatile("cp.async.commit_group;\n"); }
__device__ __forceinline__ void cp_wait0()  { asm volatile("cp.async.wait_group 0;\n"); }
__device__ __forceinline__ void cp_wait1()  { asm volatile("cp.async.wait_group 1;\n"); }

__device__ __forceinline__ void ldm_x4(uint32_t* r, uint32_t saddr) {
    asm volatile("ldmatrix.sync.aligned.m8n8.x4.shared.b16 {%0,%1,%2,%3}, [%4];"
                 : "=r"(r[0]), "=r"(r[1]), "=r"(r[2]), "=r"(r[3]) : "r"(saddr));
}
__device__ __forceinline__ void mma16816(float* c, const uint32_t* a, const uint32_t* b) {
    asm volatile("mma.sync.aligned.m16n8k16.row.col.f32.bf16.bf16.f32 "
                 "{%0,%1,%2,%3},{%4,%5,%6,%7},{%8,%9},{%0,%1,%2,%3};\n"
                 : "+f"(c[0]), "+f"(c[1]), "+f"(c[2]), "+f"(c[3])
                 : "r"(a[0]), "r"(a[1]), "r"(a[2]), "r"(a[3]), "r"(b[0]), "r"(b[1]));
}
__device__ __forceinline__ float tanh_f(float x) {
    float y; asm("tanh.approx.f32 %0, %1;" : "=f"(y) : "f"(x)); return y;
}
__device__ __forceinline__ float sig_f(float x) { return 1.f / (1.f + __expf(-x)); }
__device__ __forceinline__ int ld_acq(const int* p) {
    int v; asm volatile("ld.acquire.gpu.global.b32 %0, [%1];" : "=r"(v) : "l"(p)); return v;
}
__device__ __forceinline__ void red_release(int* p, int v) {
    asm volatile("red.release.gpu.global.add.s32 [%0], %1;" :: "l"(p), "r"(v));
}

__global__ void k_reset() { if (threadIdx.x < 2) g_cnt[threadIdx.x] = 0; }

__global__ void k_prep(const float* wihf, const float* whhf, const float* bihf,
                       const float* bhhf, const float* wihb, const float* whhb,
                       const float* bihb, const float* bhhb, const float* fcw) {
    int id = blockIdx.x * blockDim.x + threadIdx.x;
    int st = gridDim.x * blockDim.x;
    const int NW = NG * EMBD;
    for (int i = id; i < NW; i += st) {
        g_Wih[i]      = __float2bfloat16(wihf[i]);
        g_Wih[NW + i] = __float2bfloat16(wihb[i]);
        g_Whh[i]      = __float2bfloat16(whhf[i]);
        g_Whh[NW + i] = __float2bfloat16(whhb[i]);
    }
    for (int i = id; i < NG; i += st) {
        g_bias[i]      = bihf[i] + bhhf[i];
        g_bias[NG + i] = bihb[i] + bhhb[i];
    }
    for (int i = id; i < 128 * 1024; i += st) {
        int l = i >> 10, k = i & 1023;
        g_fcw[i] = __float2bfloat16(l < LT ? fcw[l * 1024 + k] : 0.f);
    }
}

__global__ void k_gather(const float* emb, const int* x) {
    int id = blockIdx.x * 256 + threadIdx.x;
    int m = id >> 6, ch = id & 63;
    int t = m >> 6, b = m & 63;
    int tok = x[b * TLEN + t];
    const float4* s = (const float4*)(emb + (size_t)tok * EMBD + ch * 8);
    float4 u = s[0], v = s[1];
    __nv_bfloat162 pk[4];
    pk[0] = __float22bfloat162_rn(make_float2(u.x, u.y));
    pk[1] = __float22bfloat162_rn(make_float2(u.z, u.w));
    pk[2] = __float22bfloat162_rn(make_float2(v.x, v.y));
    pk[3] = __float22bfloat162_rn(make_float2(v.z, v.w));
    *(uint4*)(g_A + (size_t)m * EMBD + ch * 8) = *(const uint4*)pk;
}

// mode 0: G = A @ Wih^T + bias (bf16, gate-major). mode 1: em = H @ fcw^T + fcb.
__global__ void __launch_bounds__(256, 2) k_gemm(int mode, const float* fcb) {
    __shared__ __nv_bfloat16 As[2][128 * 40];
    __shared__ __nv_bfloat16 Bs[2][128 * 40];
    int tid = threadIdx.x, lane = tid & 31, warp = tid >> 5;
    int wm = warp >> 2, wn = warp & 3;
    int m0 = blockIdx.y * 128, n0 = blockIdx.x * 128;
    int KC = mode ? 32 : 16;

    int ra = wm * 64 + (lane & 7) + ((lane >> 3) & 1) * 8;
    int ca = (lane >> 4) * 8;
    int rb = wn * 32 + (lane & 7) + ((lane >> 4) & 1) * 8;
    int cb = ((lane >> 3) & 1) * 8;
    uint32_t sAb[2] = {(uint32_t)__cvta_generic_to_shared(&As[0][0]),
                       (uint32_t)__cvta_generic_to_shared(&As[1][0])};
    uint32_t sBb[2] = {(uint32_t)__cvta_generic_to_shared(&Bs[0][0]),
                       (uint32_t)__cvta_generic_to_shared(&Bs[1][0])};

    float acc[4][4][4];
    #pragma unroll
    for (int a = 0; a < 4; a++)
        #pragma unroll
        for (int b = 0; b < 4; b++)
            #pragma unroll
            for (int c = 0; c < 4; c++) acc[a][b][c] = 0.f;

    auto load_stage = [&](int kc, int s) {
        #pragma unroll
        for (int i = 0; i < 2; i++) {
            int c = tid + i * 256;
            int row = c >> 2, seg = c & 3;
            const __nv_bfloat16* sa;
            if (mode == 0)
                sa = g_A + (size_t)(m0 + row) * 512 + kc * 32 + seg * 8;
            else if (kc < 16)
                sa = g_H + (size_t)(m0 + row) * 512 + kc * 32 + seg * 8;
            else
                sa = g_H + (size_t)MR * HD + (size_t)(m0 + row) * 512 + (kc - 16) * 32 + seg * 8;
            cp_async16(&As[s][row * 40 + seg * 8], sa);
            const __nv_bfloat16* sb;
            if (mode == 0)
                sb = g_Wih + (size_t)(n0 + row) * 512 + kc * 32 + seg * 8;
            else
                sb = g_fcw + (size_t)(n0 + row) * 1024 + kc * 32 + seg * 8;
            cp_async16(&Bs[s][row * 40 + seg * 8], sb);
        }
    };

    load_stage(0, 0); cp_commit();
    for (int kc = 0; kc < KC; kc++) {
        int s = kc & 1;
        if (kc + 1 < KC) { load_stage(kc + 1, s ^ 1); cp_commit(); cp_wait1(); }
        else cp_wait0();
        __syncthreads();
        #pragma unroll
        for (int kk = 0; kk < 32; kk += 16) {
            uint32_t a[4][4], bq[2][4];
            #pragma unroll
            for (int mi = 0; mi < 4; mi++)
                ldm_x4(a[mi], sAb[s] + ((ra + mi * 16) * 40 + ca + kk) * 2);
            #pragma unroll
            for (int np = 0; np < 2; np++)
                ldm_x4(bq[np], sBb[s] + ((rb + np * 16) * 40 + cb + kk) * 2);
            #pragma unroll
            for (int mi = 0; mi < 4; mi++)
                #pragma unroll
                for (int ni = 0; ni < 4; ni++)
                    mma16816(acc[mi][ni], a[mi], &bq[ni >> 1][(ni & 1) * 2]);
        }
        __syncthreads();
    }

    #pragma unroll
    for (int mi = 0; mi < 4; mi++) {
        #pragma unroll
        for (int ni = 0; ni < 4; ni++) {
            int m = m0 + wm * 64 + mi * 16 + (lane >> 2);
            int n = n0 + wn * 32 + ni * 8 + (lane & 3) * 2;
            if (mode == 0) {
                int dir = n >> 11, r = n & 2047;
                size_t o1 = ((size_t)dir * MR + m) * NG + r;
                size_t o2 = ((size_t)dir * MR + m + 8) * NG + r;
                float b0 = g_bias[n], b1 = g_bias[n + 1];
                *(__nv_bfloat162*)&g_G[o1] = __float22bfloat162_rn(
                    make_float2(acc[mi][ni][0] + b0, acc[mi][ni][1] + b1));
                *(__nv_bfloat162*)&g_G[o2] = __float22bfloat162_rn(
                    make_float2(acc[mi][ni][2] + b0, acc[mi][ni][3] + b1));
            } else {
                if (n < LT) {
                    g_em[(size_t)m * LT + n]       = acc[mi][ni][0] + fcb[n];
                    g_em[(size_t)(m + 8) * LT + n] = acc[mi][ni][2] + fcb[n];
                }
                if (n + 1 < LT) {
                    g_em[(size_t)m * LT + n + 1]       = acc[mi][ni][1] + fcb[n + 1];
                    g_em[(size_t)(m + 8) * LT + n + 1] = acc[mi][ni][3] + fcb[n + 1];
                }
            }
        }
    }
}

// Persistent LSTM: 128 CTAs (dir=blk>>6), 8 channels each.
// Whh columns interleaved in SMEM so MMA fragments feed pointwise directly:
//   column j: gate(j) = (j&1) | ((j>>3)&1)<<1 ; ch(j) = (j>>4)*4 + ((j&7)>>1)
__global__ void __launch_bounds__(256, 1) k_lstm() {
    extern __shared__ char smem[];
    __nv_bfloat16* whh_s = (__nv_bfloat16*)smem;           // 32 x 520
    __nv_bfloat16* hp_s  = whh_s + 32 * 520;               // 64 x 520

    int tid = threadIdx.x, lane = tid & 31, warp = tid >> 5;
    int dir = blockIdx.x >> 6, cta = blockIdx.x & 63, c0 = cta * 8;
    int wm = warp & 3, wn = warp >> 2;

    for (int i = tid; i < 32 * 512; i += 256) {
        int j = i >> 9, k = i & 511;
        int gate = (j & 1) | (((j >> 3) & 1) << 1);
        int ch   = ((j >> 4) << 2) | ((j & 7) >> 1);
        int r = (gate << 9) + c0 + ch;
        whh_s[j * 520 + k] = g_Whh[((size_t)dir * NG + r) * HD + k];
    }
    __syncthreads();

    uint32_t hpB  = (uint32_t)__cvta_generic_to_shared(hp_s);
    uint32_t whhB = (uint32_t)__cvta_generic_to_shared(whh_s);
    int ra = wm * 16 + (lane & 7) + ((lane >> 3) & 1) * 8;
    int ca = (lane >> 4) * 8;
    int rb = wn * 16 + (lane & 7) + ((lane >> 4) & 1) * 8;
    int cb = ((lane >> 3) & 1) * 8;
    uint32_t aAddr = hpB  + (ra * 520 + ca) * 2;
    uint32_t bAddr = whhB + (rb * 520 + cb) * 2;

    int r0  = wm * 16 + (lane >> 2);              // batch rows r0, r0+8
    int chg = c0 + wn * 4 + (lane & 3);           // this thread's channel
    float cs0 = 0.f, cs1 = 0.f;
    const __nv_bfloat16* Gbase = g_G + (size_t)dir * MR * NG;

    for (int s = 0; s < TLEN; s++) {
        int t = dir ? (TLEN - 1 - s) : s;
        // gate-major G: 8 scalar loads, issued before the poll (off critical path)
        const __nv_bfloat16* Gp = Gbase + ((size_t)t * 64 + r0) * NG + chg;
        float gi0 = __bfloat162float(__ldg(Gp));
        float gf0 = __bfloat162float(__ldg(Gp + 512));
        float gg0 = __bfloat162float(__ldg(Gp + 1024));
        float go0 = __bfloat162float(__ldg(Gp + 1536));
        float gi1 = __bfloat162float(__ldg(Gp + 8 * 2048));
        float gf1 = __bfloat162float(__ldg(Gp + 8 * 2048 + 512));
        float gg1 = __bfloat162float(__ldg(Gp + 8 * 2048 + 1024));
        float go1 = __bfloat162float(__ldg(Gp + 8 * 2048 + 1536));

        float c[2][4] = {{0, 0, 0, 0}, {0, 0, 0, 0}};
        if (s > 0) {
            if (tid == 0) { while (ld_acq(&g_cnt[dir]) < s * 64) { } }
            __syncthreads();
            int pt = dir ? t + 1 : t - 1;
            const __nv_bfloat16* Hs = g_H + ((size_t)dir * MR + (size_t)pt * 64) * HD;
            for (int i = tid; i < 2048; i += 256) {          // k 0..255
                int b = i >> 5, seg = i & 31;
                cp_async16(&hp_s[b * 520 + seg * 8], Hs + (size_t)b * 512 + seg * 8);
            }
            cp_commit();
            for (int i = tid; i < 2048; i += 256) {          // k 256..511
                int b = i >> 5, seg = i & 31;
                cp_async16(&hp_s[b * 520 + 256 + seg * 8], Hs + (size_t)b * 512 + 256 + seg * 8);
            }
            cp_commit();
            cp_wait1();
            __syncthreads();
            #pragma unroll 4
            for (int kk = 0; kk < 256; kk += 16) {
                uint32_t a[4], bfr[4];
                ldm_x4(a,   aAddr + kk * 2);
                ldm_x4(bfr, bAddr + kk * 2);
                mma16816(c[0], a, bfr);
                mma16816(c[1], a, bfr + 2);
            }
            cp_wait0();
            __syncthreads();
            #pragma unroll 4
            for (int kk = 256; kk < 512; kk += 16) {
                uint32_t a[4], bfr[4];
                ldm_x4(a,   aAddr + kk * 2);
                ldm_x4(bfr, bAddr + kk * 2);
                mma16816(c[0], a, bfr);
                mma16816(c[1], a, bfr + 2);
            }
        }

        // pointwise straight from fragments: c[0]={i,f}, c[1]={g,o}; [2],[3] = row+8
        float i0 = gi0 + c[0][0], f0 = gf0 + c[0][1];
        float g0 = gg0 + c[1][0], o0 = go0 + c[1][1];
        float i1 = gi1 + c[0][2], f1 = gf1 + c[0][3];
        float g1 = gg1 + c[1][2], o1 = go1 + c[1][3];
        cs0 = sig_f(f0) * cs0 + sig_f(i0) * tanh_f(g0);
        cs1 = sig_f(f1) * cs1 + sig_f(i1) * tanh_f(g1);
        float h0 = sig_f(o0) * tanh_f(cs0);
        float h1 = sig_f(o1) * tanh_f(cs1);
        __nv_bfloat16* Hd = g_H + ((size_t)dir * MR + (size_t)t * 64 + r0) * HD + chg;
        Hd[0]       = __float2bfloat16(h0);
        Hd[8 * 512] = __float2bfloat16(h1);
        __syncthreads();
        if (tid == 0) red_release(&g_cnt[dir], 1);
    }
}

// CRF: 64 CTAs x 64 threads; thread j owns tag j; exp(trans) column in registers;
// incremental shift removes the per-step max reduction.
__global__ void __launch_bounds__(64) k_crf(const float* strans, const float* etrans,
                                            const float* trans, const int* tags) {
    __shared__ float p_s[48];
    __shared__ float v0_s;
    __shared__ float red[64];
    int b = blockIdx.x, tid = threadIdx.x;
    bool act = tid < LT;

    float Et[48];
    if (act) {
        #pragma unroll 8
        for (int i = 0; i < 48; i++) Et[i] = __expf(trans[i * 48 + tid]);
    }
    float num = 0.f;
    for (int t = tid; t < TLEN; t += 64) {
        int tg = tags[b * TLEN + t];
        num += g_em[((size_t)t * 64 + b) * LT + tg];
        num += (t > 0) ? trans[tags[b * TLEN + t - 1] * 48 + tg] : strans[tg];
        if (t == TLEN - 1) num += etrans[tg];
    }
    red[tid] = num; __syncthreads();
    for (int o = 32; o > 0; o >>= 1) { if (tid < o) red[tid] += red[tid + o]; __syncthreads(); }
    num = red[0];
    __syncthreads();

    float ah = 0.f, S = 0.f;
    {
        float a0 = act ? (strans[tid] + g_em[(size_t)b * LT + tid]) : 0.f;
        if (tid == 0) v0_s = a0;
        __syncthreads();
        S = v0_s;
        ah = a0 - v0_s;
        __syncthreads();
    }
    for (int t = 1; t < TLEN; t++) {
        float e = act ? g_em[((size_t)t * 64 + b) * LT + tid] : 0.f;
        if (act) p_s[tid] = __expf(ah);
        __syncthreads();
        float v = 0.f;
        if (act) {
            float dot = 0.f;
            #pragma unroll 12
            for (int i = 0; i < 48; i++) dot += p_s[i] * Et[i];
            v = e + __logf(dot);
            if (tid == 0) v0_s = v;
        }
        __syncthreads();
        ah = v - v0_s;
        S += v0_s;
    }
    float fv = act ? (ah + etrans[tid]) : -1e30f;
    red[tid] = fv; __syncthreads();
    for (int o = 32; o > 0; o >>= 1) { if (tid < o) red[tid] = fmaxf(red[tid], red[tid + o]); __syncthreads(); }
    float mx = red[0]; __syncthreads();
    red[tid] = act ? __expf(fv - mx) : 0.f; __syncthreads();
    for (int o = 32; o > 0; o >>= 1) { if (tid < o) red[tid] += red[tid + o]; __syncthreads(); }
    if (tid == 0) g_llh[b] = num - (S + mx + __logf(red[0]));
}

__global__ void k_fin(float* out) {
    __shared__ float red[64];
    red[threadIdx.x] = g_llh[threadIdx.x]; __syncthreads();
    for (int o = 32; o > 0; o >>= 1) {
        if (threadIdx.x < o) red[threadIdx.x] += red[threadIdx.x + o];
        __syncthreads();
    }
    if (threadIdx.x == 0) out[0] = -red[0] / 64.f;
}

extern "C" void kernel_launch(void* const* d_in, const int* in_sizes, int n_in,
                              void* d_out, int out_size) {
    const float* emb    = (const float*)d_in[0];
    const float* wihf   = (const float*)d_in[1];
    const float* whhf   = (const float*)d_in[2];
    const float* bihf   = (const float*)d_in[3];
    const float* bhhf   = (const float*)d_in[4];
    const float* wihb   = (const float*)d_in[5];
    const float* whhb   = (const float*)d_in[6];
    const float* bihb   = (const float*)d_in[7];
    const float* bhhb   = (const float*)d_in[8];
    const float* fcw    = (const float*)d_in[9];
    const float* fcb    = (const float*)d_in[10];
    const float* strans = (const float*)d_in[11];
    const float* etrans = (const float*)d_in[12];
    const float* trans  = (const float*)d_in[13];
    const int*   x      = (const int*)d_in[14];
    const int*   tags   = (const int*)d_in[15];
    float* out = (float*)d_out;

    const int lstm_smem = 32 * 520 * 2 + 64 * 520 * 2;
    cudaFuncSetAttribute(k_lstm, cudaFuncAttributeMaxDynamicSharedMemorySize, lstm_smem);

    k_reset<<<1, 32>>>();
    k_prep<<<2048, 256>>>(wihf, whhf, bihf, bhhf, wihb, whhb, bihb, bhhb, fcw);
    k_gather<<<8192, 256>>>(emb, x);
    k_gemm<<<dim3(32, 256), 256>>>(0, fcb);
    k_lstm<<<128, 256, lstm_smem>>>();
    k_gemm<<<dim3(1, 256), 256>>>(1, fcb);
    k_crf<<<64, 64>>>(strans, etrans, trans, tags);
    k_fin<<<1, 64>>>(out);
}